// round 2
// baseline (speedup 1.0000x reference)
#include <cuda_runtime.h>
#include <cstdint>
#include <math.h>

// Binary MLP: B=16384, D=H=1024, C=10.
// Strategy: bit-pack all ±1 tensors (bit=1 <=> +1). Hidden layers are
// XOR+POPC GEMMs with the BatchNorm+binarize epilogue folded into a single
// per-neuron integer threshold on the popcount P (computed exactly in double
// on-device). Output words are produced directly via __ballot_sync.

#define NB       16384          // batch rows
#define KW       32             // 1024 bits / 32 = words per row
#define HN       1024           // hidden neurons
#define ROWS_PB  128            // rows per block (layer kernel)
#define GRP_PB   8              // neuron groups (of 32) per block
#define THREADS  256

// Scratch (device globals: allocation-free rule)
__device__ unsigned g_act[2][NB * KW];     // ping-pong packed activations (2 x 2MB)
__device__ unsigned g_wt[3][KW * HN];      // packed hidden weights, transposed: [word j][neuron n]
__device__ unsigned g_w4[10 * KW];         // packed output weights [c][j]

// ---------------- input packing: bit = (2x-1 >= 0) ----------------
__global__ void pack_x_kernel(const float* __restrict__ x) {
    int t = blockIdx.x * blockDim.x + threadIdx.x;   // one thread per output word
    if (t >= NB * KW) return;
    int row = t >> 5;
    int w   = t & 31;
    const float4* p = reinterpret_cast<const float4*>(x + (size_t)row * 1024 + w * 32);
    unsigned bits = 0;
#pragma unroll
    for (int i = 0; i < 8; i++) {
        float4 v = p[i];
        bits |= ((2.0f * v.x - 1.0f) >= 0.0f ? 1u : 0u) << (4 * i + 0);
        bits |= ((2.0f * v.y - 1.0f) >= 0.0f ? 1u : 0u) << (4 * i + 1);
        bits |= ((2.0f * v.z - 1.0f) >= 0.0f ? 1u : 0u) << (4 * i + 2);
        bits |= ((2.0f * v.w - 1.0f) >= 0.0f ? 1u : 0u) << (4 * i + 3);
    }
    g_act[0][t] = bits;
}

// ---------------- weight packing (transposed): wt[j][n] bit l = (W[n][32j+l] >= 0) ----
__global__ void pack_w_kernel(const float* __restrict__ W, int widx) {
    int t = blockIdx.x * blockDim.x + threadIdx.x;   // 32*1024 threads
    if (t >= KW * HN) return;
    int n = t & (HN - 1);
    int j = t >> 10;
    const float4* p = reinterpret_cast<const float4*>(W + (size_t)n * 1024 + j * 32);
    unsigned bits = 0;
#pragma unroll
    for (int i = 0; i < 8; i++) {
        float4 v = p[i];
        bits |= (v.x >= 0.0f ? 1u : 0u) << (4 * i + 0);
        bits |= (v.y >= 0.0f ? 1u : 0u) << (4 * i + 1);
        bits |= (v.z >= 0.0f ? 1u : 0u) << (4 * i + 2);
        bits |= (v.w >= 0.0f ? 1u : 0u) << (4 * i + 3);
    }
    g_wt[widx][j * HN + n] = bits;
}

__global__ void pack_w4_kernel(const float* __restrict__ W4) {
    int t = threadIdx.x;                             // 320 threads
    if (t >= 10 * KW) return;
    int c = t >> 5;
    int j = t & 31;
    const float4* p = reinterpret_cast<const float4*>(W4 + (size_t)c * 1024 + j * 32);
    unsigned bits = 0;
#pragma unroll
    for (int i = 0; i < 8; i++) {
        float4 v = p[i];
        bits |= (v.x >= 0.0f ? 1u : 0u) << (4 * i + 0);
        bits |= (v.y >= 0.0f ? 1u : 0u) << (4 * i + 1);
        bits |= (v.z >= 0.0f ? 1u : 0u) << (4 * i + 2);
        bits |= (v.w >= 0.0f ? 1u : 0u) << (4 * i + 3);
    }
    g_w4[c * KW + j] = bits;
}

// ---------------- hidden layer: binary GEMM + BN threshold + repack ----------------
// grid: (NB/ROWS_PB, HN/(GRP_PB*32)), block: 256 (8 warps, 1 neuron-group each)
__global__ void __launch_bounds__(THREADS)
layer_kernel(int src, int dst, int widx,
             const float* __restrict__ gg, const float* __restrict__ bb,
             const float* __restrict__ mm, const float* __restrict__ vv) {
    __shared__ uint4 sh_a[ROWS_PB][8];

    const int tid  = threadIdx.x;
    const int lane = tid & 31;
    const int wid  = tid >> 5;
    const int row0 = blockIdx.x * ROWS_PB;
    const int grp  = blockIdx.y * GRP_PB + wid;      // this warp's 32-neuron group
    const int n    = grp * 32 + lane;                // this lane's neuron

    // stage A tile: ROWS_PB rows x 32 words = 1024 uint4
    {
        const uint4* asrc = reinterpret_cast<const uint4*>(&g_act[src][(size_t)row0 * KW]);
        uint4* adst = &sh_a[0][0];
        for (int i = tid; i < ROWS_PB * 8; i += THREADS) adst[i] = asrc[i];
    }

    // per-lane weight cache (32 regs) — loads coalesced across lanes
    unsigned w[KW];
    const unsigned* wt = &g_wt[widx][0];
#pragma unroll
    for (int j = 0; j < KW; j++) w[j] = wt[j * HN + n];

    // exact integer threshold from BN params:
    // pre = ((1024-2P) - m)*scale + b >= 0,  scale = g / sqrt(v + 1e-5)
    // scale>0: bit = (P <= floor(T));  scale<0: bit = (P >= ceil(T)) = !(P <= ceil(T)-1)
    // with T = (1024 - m + b/scale) / 2
    int thr; unsigned neg;
    {
        double gd = (double)gg[n], vd = (double)vv[n];
        double md = (double)mm[n], bd = (double)bb[n];
        double sc = gd / sqrt(vd + 1e-5);
        if (sc > 0.0) {
            double T = (1024.0 - md + bd / sc) * 0.5;
            T = fmin(fmax(T, -2.0e9), 2.0e9);
            thr = (int)floor(T); neg = 0u;
        } else if (sc < 0.0) {
            double T = (1024.0 - md + bd / sc) * 0.5;
            T = fmin(fmax(T, -2.0e9), 2.0e9);
            thr = (int)ceil(T) - 1; neg = 1u;
        } else {
            thr = (bd >= 0.0) ? 0x7fffffff : (-0x7fffffff - 1); neg = 0u;
        }
    }
    __syncthreads();

    unsigned* out = &g_act[dst][0];
#pragma unroll 2
    for (int r = 0; r < ROWS_PB; ++r) {
        int a0 = 0, a1 = 0, a2 = 0, a3 = 0;
#pragma unroll
        for (int i = 0; i < 8; i++) {
            uint4 av = sh_a[r][i];                   // broadcast LDS.128
            a0 += __popc(av.x ^ w[4 * i + 0]);
            a1 += __popc(av.y ^ w[4 * i + 1]);
            a2 += __popc(av.z ^ w[4 * i + 2]);
            a3 += __popc(av.w ^ w[4 * i + 3]);
        }
        int P = (a0 + a1) + (a2 + a3);
        unsigned bit = ((P <= thr) ? 1u : 0u) ^ neg;
        unsigned wordbits = __ballot_sync(0xffffffffu, bit != 0u);
        if (lane == 0) out[(size_t)(row0 + r) * KW + grp] = wordbits;
    }
}

// ---------------- final layer (C=10) + TensorNorm ----------------
__global__ void final_kernel(const float* __restrict__ tnw, const float* __restrict__ tnb,
                             const float* __restrict__ tnm, const float* __restrict__ tnv,
                             float* __restrict__ out) {
    __shared__ unsigned sw[10 * KW];
    const int tid = threadIdx.x;
    for (int i = tid; i < 10 * KW; i += blockDim.x) sw[i] = g_w4[i];
    __syncthreads();

    int row = blockIdx.x * blockDim.x + tid;
    if (row >= NB) return;

    uint4 a[8];
    const uint4* p = reinterpret_cast<const uint4*>(&g_act[1][(size_t)row * KW]);
#pragma unroll
    for (int i = 0; i < 8; i++) a[i] = p[i];

    float rs = (float)(1.0 / sqrt((double)tnv[0] + 1e-4));
    float wq = tnw[0], bq = tnb[0], mq = tnm[0];

#pragma unroll
    for (int c = 0; c < 10; c++) {
        int P = 0;
#pragma unroll
        for (int i = 0; i < 8; i++) {
            P += __popc(a[i].x ^ sw[c * KW + 4 * i + 0]);
            P += __popc(a[i].y ^ sw[c * KW + 4 * i + 1]);
            P += __popc(a[i].z ^ sw[c * KW + 4 * i + 2]);
            P += __popc(a[i].w ^ sw[c * KW + 4 * i + 3]);
        }
        float s = (float)(1024 - 2 * P);
        out[(size_t)row * 10 + c] = ((s - mq) * rs) * wq + bq;
    }
}

extern "C" void kernel_launch(void* const* d_in, const int* in_sizes, int n_in,
                              void* d_out, int out_size) {
    const float* x  = (const float*)d_in[0];
    const float* W1 = (const float*)d_in[1];
    const float* W2 = (const float*)d_in[2];
    const float* W3 = (const float*)d_in[3];
    const float* W4 = (const float*)d_in[4];
    const float* g1 = (const float*)d_in[5],  *b1 = (const float*)d_in[6];
    const float* m1 = (const float*)d_in[7],  *v1 = (const float*)d_in[8];
    const float* g2 = (const float*)d_in[9],  *b2 = (const float*)d_in[10];
    const float* m2 = (const float*)d_in[11], *v2 = (const float*)d_in[12];
    const float* g3 = (const float*)d_in[13], *b3 = (const float*)d_in[14];
    const float* m3 = (const float*)d_in[15], *v3 = (const float*)d_in[16];
    const float* tnw = (const float*)d_in[17], *tnb = (const float*)d_in[18];
    const float* tnm = (const float*)d_in[19], *tnv = (const float*)d_in[20];
    float* out = (float*)d_out;

    // packing
    pack_x_kernel<<<(NB * KW + 255) / 256, 256>>>(x);
    pack_w_kernel<<<(KW * HN + 255) / 256, 256>>>(W1, 0);
    pack_w_kernel<<<(KW * HN + 255) / 256, 256>>>(W2, 1);
    pack_w_kernel<<<(KW * HN + 255) / 256, 256>>>(W3, 2);
    pack_w4_kernel<<<1, 320>>>(W4);

    dim3 lgrid(NB / ROWS_PB, HN / (GRP_PB * 32));    // (128, 4)
    layer_kernel<<<lgrid, THREADS>>>(0, 1, 0, g1, b1, m1, v1);
    layer_kernel<<<lgrid, THREADS>>>(1, 0, 1, g2, b2, m2, v2);
    layer_kernel<<<lgrid, THREADS>>>(0, 1, 2, g3, b3, m3, v3);

    final_kernel<<<NB / 256, 256>>>(tnw, tnb, tnm, tnv, out);
}